// round 7
// baseline (speedup 1.0000x reference)
#include <cuda_runtime.h>
#include <cuda_bf16.h>

// Problem constants (fixed by the dataset)
#define NN      100000
#define NE      1600000
#define F_IN    128
#define F_HID   64
#define F_OUT   64

// -------- scratch (device globals; no allocation allowed) --------
__device__ __align__(16) float d_g   [NN * 64];  // (h @ W) * dis[row]   (per layer)
__device__ __align__(16) float d_agg [NN * 64];  // scatter accumulator
__device__ __align__(16) float d_h   [NN * 64];  // layer-1 output (post relu)
__device__ __align__(16) float d_sums[NN * 64];  // scatter-mean sums
__device__ int   d_src[NE];
__device__ int   d_dst[NE];
__device__ int   d_user[NN];
__device__ float d_dis[NN];
__device__ int   d_deg[NN];
__device__ int   d_cnt[NN];
__device__ int   d_odd_or;     // 0 after detect => indices are int64

// 16-byte vector atomic add to global, explicit cvta so the address space is
// unambiguous (red.global with a guaranteed-global address).
__device__ __forceinline__ void atomic_add_f4(float* addr, float4 v) {
    unsigned long long ga;
    asm("cvta.to.global.u64 %0, %1;" : "=l"(ga) : "l"(addr));
    asm volatile("red.global.add.v4.f32 [%0], {%1, %2, %3, %4};"
                 :: "l"(ga), "f"(v.x), "f"(v.y), "f"(v.z), "f"(v.w) : "memory");
}

// ---------------------------------------------------------------
// Zero all per-replay scratch (graph-replay safe; no memset nodes).
__global__ void zero_init() {
    int t = blockIdx.x * blockDim.x + threadIdx.x;   // NN*16 float4 slots
    if (t == 0) d_odd_or = 0;
    if (t < NN * 16) {
        ((float4*)d_agg)[t]  = make_float4(0.f, 0.f, 0.f, 0.f);
        ((float4*)d_sums)[t] = make_float4(0.f, 0.f, 0.f, 0.f);
    }
    if (t < NN / 4) {                                 // NN divisible by 4
        ((int4*)d_deg)[t] = make_int4(0, 0, 0, 0);
        ((int4*)d_cnt)[t] = make_int4(0, 0, 0, 0);
    }
}

// ---------------------------------------------------------------
// Detect index dtype: OR the odd 32-bit words of the first 2048 entries.
// int64 data (values < 2^31, nonneg) -> all high words zero -> d_odd_or == 0.
// int32 data -> odd words are random node ids -> OR is nonzero w.p. ~1.
__global__ void detect_kernel(const int* __restrict__ ei_words) {
    int x = 0;
    for (int i = threadIdx.x; i < 2048; i += blockDim.x)
        x |= ei_words[2 * i + 1];
    x |= __shfl_xor_sync(0xffffffff, x, 16);
    x |= __shfl_xor_sync(0xffffffff, x, 8);
    x |= __shfl_xor_sync(0xffffffff, x, 4);
    x |= __shfl_xor_sync(0xffffffff, x, 2);
    x |= __shfl_xor_sync(0xffffffff, x, 1);
    if ((threadIdx.x & 31) == 0 && x) atomicOr(&d_odd_or, 1);
}

// ---------------------------------------------------------------
// Normalize edge indices to int32, fuse degree histogram.
__global__ void convert_edges(const void* __restrict__ ei) {
    int t = blockIdx.x * blockDim.x + threadIdx.x;
    if (t >= NE) return;
    int s, d;
    if (d_odd_or == 0) {  // int64
        s = (int)((const long long*)ei)[t];
        d = (int)((const long long*)ei)[NE + t];
    } else {              // int32
        s = ((const int*)ei)[t];
        d = ((const int*)ei)[NE + t];
    }
    d_src[t] = s;
    d_dst[t] = d;
    atomicAdd(&d_deg[d], 1);
}

__global__ void convert_user(const void* __restrict__ u) {
    int t = blockIdx.x * blockDim.x + threadIdx.x;
    if (t >= NN) return;
    d_user[t] = (d_odd_or == 0) ? (int)((const long long*)u)[t]
                                : ((const int*)u)[t];
}

__global__ void dis_kernel() {
    int i = blockIdx.x * blockDim.x + threadIdx.x;
    if (i < NN) d_dis[i] = rsqrtf((float)(d_deg[i] + 1));  // +1 = self loop; always > 0
}

// ---------------------------------------------------------------
// G[r, :] = dis[r] * (X[r, :] @ W)     W is [K, 64] row-major.
// blockDim (16, 8) = 128 threads. 64 rows/block. Each thread: 8 rows x 4 cols.
template <int K>
__global__ void gemm_scale(const float* __restrict__ X, const float* __restrict__ W) {
    extern __shared__ float sm[];
    float* Ws = sm;            // K * 64
    float* Xs = sm + K * 64;   // 64 * K
    const int tid  = threadIdx.y * 16 + threadIdx.x;
    const int row0 = blockIdx.x * 64;

    // stage W
    for (int i = tid; i < K * 16; i += 128)
        ((float4*)Ws)[i] = ((const float4*)W)[i];
    // stage X tile (64 rows)
    for (int i = tid; i < 16 * K; i += 128) {
        int r = i / (K / 4), c = i % (K / 4);
        int gr = row0 + r;
        ((float4*)Xs)[i] = (gr < NN) ? ((const float4*)X)[(size_t)gr * (K / 4) + c]
                                     : make_float4(0.f, 0.f, 0.f, 0.f);
    }
    __syncthreads();

    float acc[8][4];
#pragma unroll
    for (int j = 0; j < 8; j++) { acc[j][0] = acc[j][1] = acc[j][2] = acc[j][3] = 0.f; }

    const int c0 = threadIdx.x * 4;
#pragma unroll 4
    for (int k = 0; k < K; k++) {
        float4 w = *(const float4*)&Ws[k * 64 + c0];
#pragma unroll
        for (int j = 0; j < 8; j++) {
            float xv = Xs[(threadIdx.y + j * 8) * K + k];
            acc[j][0] += xv * w.x; acc[j][1] += xv * w.y;
            acc[j][2] += xv * w.z; acc[j][3] += xv * w.w;
        }
    }
#pragma unroll
    for (int j = 0; j < 8; j++) {
        int r = row0 + threadIdx.y + j * 8;
        if (r < NN) {
            float d = d_dis[r];
            *(float4*)&d_g[(size_t)r * 64 + c0] =
                make_float4(acc[j][0] * d, acc[j][1] * d, acc[j][2] * d, acc[j][3] * d);
        }
    }
}

// ---------------------------------------------------------------
// agg[dst, :] += g[src, :]     16 threads per edge, float4 each, vector RED.
__global__ void edge_agg() {
    int t = blockIdx.x * blockDim.x + threadIdx.x;
    int e = t >> 4;
    if (e >= NE) return;
    int lane = t & 15;
    int src = d_src[e];
    int dst = d_dst[e];
    float4 v = __ldg((const float4*)(d_g + (size_t)src * 64) + lane);
    atomic_add_f4(d_agg + (size_t)dst * 64 + lane * 4, v);
}

// ---------------------------------------------------------------
// h = relu(dis * (agg + g) + b1); re-zero agg in place for layer 2.
__global__ void finalize1(const float* __restrict__ b1) {
    int t = blockIdx.x * blockDim.x + threadIdx.x;   // NN*16 float4s
    if (t >= NN * 16) return;
    int r = t >> 4, lane = t & 15;
    float d  = d_dis[r];
    float4 a = *((const float4*)(d_agg + (size_t)r * 64) + lane);
    *((float4*)(d_agg + (size_t)r * 64) + lane) = make_float4(0.f, 0.f, 0.f, 0.f);
    float4 g = *((const float4*)(d_g   + (size_t)r * 64) + lane);
    float4 b = ((const float4*)b1)[lane];
    float4 o;
    o.x = fmaxf(fmaf(d, a.x + g.x, b.x), 0.f);
    o.y = fmaxf(fmaf(d, a.y + g.y, b.y), 0.f);
    o.z = fmaxf(fmaf(d, a.z + g.z, b.z), 0.f);
    o.w = fmaxf(fmaf(d, a.w + g.w, b.w), 0.f);
    *((float4*)(d_h + (size_t)r * 64) + lane) = o;
}

// ---------------------------------------------------------------
// v = dis * (agg + g) + b2 ; sums[user[r], :] += v ; cnt[user[r]] += 1
__global__ void finalize2_scatter(const float* __restrict__ b2) {
    int t = blockIdx.x * blockDim.x + threadIdx.x;
    if (t >= NN * 16) return;
    int r = t >> 4, lane = t & 15;
    float d  = d_dis[r];
    float4 a = *((const float4*)(d_agg + (size_t)r * 64) + lane);
    float4 g = *((const float4*)(d_g   + (size_t)r * 64) + lane);
    float4 b = ((const float4*)b2)[lane];
    float4 v;
    v.x = fmaf(d, a.x + g.x, b.x);
    v.y = fmaf(d, a.y + g.y, b.y);
    v.z = fmaf(d, a.z + g.z, b.z);
    v.w = fmaf(d, a.w + g.w, b.w);
    int u = d_user[r];
    atomic_add_f4(d_sums + (size_t)u * 64 + lane * 4, v);
    if (lane == 0) atomicAdd(&d_cnt[u], 1);
}

// ---------------------------------------------------------------
// out[u, :] = cnt[u] > 0 ? sums[u, :] / cnt[u] : 0
__global__ void out_mean(float* __restrict__ out) {
    int t = blockIdx.x * blockDim.x + threadIdx.x;
    if (t >= NN * 16) return;
    int r = t >> 4, lane = t & 15;
    int c = d_cnt[r];
    float4 s = *((const float4*)(d_sums + (size_t)r * 64) + lane);
    float4 o = make_float4(0.f, 0.f, 0.f, 0.f);
    if (c > 0) {
        float inv = 1.0f / (float)c;
        o = make_float4(s.x * inv, s.y * inv, s.z * inv, s.w * inv);
    }
    *((float4*)(out + (size_t)r * 64) + lane) = o;
}

// ---------------------------------------------------------------
extern "C" void kernel_launch(void* const* d_in, const int* in_sizes, int n_in,
                              void* d_out, int out_size) {
    const float* x    = (const float*)d_in[0];
    const void*  ei   = d_in[1];
    const void*  uidx = d_in[2];
    const float* W1   = (const float*)d_in[3];
    const float* b1   = (const float*)d_in[4];
    const float* W2   = (const float*)d_in[5];
    const float* b2   = (const float*)d_in[6];
    float*       out  = (float*)d_out;
    (void)in_sizes; (void)n_in; (void)out_size;

    // gemm<128> needs 64KB dynamic smem (> 48KB default)
    cudaFuncSetAttribute(gemm_scale<128>, cudaFuncAttributeMaxDynamicSharedMemorySize,
                         (128 * 64 + 64 * 128) * (int)sizeof(float));

    void* p_h;
    cudaGetSymbolAddress(&p_h, d_h);   // host-side query, not a stream op

    const int TB = 256;

    // zero scratch, detect index dtype, normalize indices, degrees / norm
    zero_init<<<(NN * 16 + TB - 1) / TB, TB>>>();
    detect_kernel<<<1, 256>>>((const int*)ei);
    convert_edges<<<(NE + TB - 1) / TB, TB>>>(ei);
    convert_user<<<(NN + TB - 1) / TB, TB>>>(uidx);
    dis_kernel<<<(NN + TB - 1) / TB, TB>>>();

    // ---- layer 1 ----
    gemm_scale<128><<<(NN + 63) / 64, dim3(16, 8),
                      (128 * 64 + 64 * 128) * sizeof(float)>>>(x, W1);
    edge_agg<<<(NE * 16 + TB - 1) / TB, TB>>>();
    finalize1<<<(NN * 16 + TB - 1) / TB, TB>>>(b1);   // also re-zeros d_agg

    // ---- layer 2 ----
    gemm_scale<64><<<(NN + 63) / 64, dim3(16, 8),
                     (64 * 64 + 64 * 64) * sizeof(float)>>>((const float*)p_h, W2);
    edge_agg<<<(NE * 16 + TB - 1) / TB, TB>>>();

    // ---- scatter-mean ----
    finalize2_scatter<<<(NN * 16 + TB - 1) / TB, TB>>>(b2);
    out_mean<<<(NN * 16 + TB - 1) / TB, TB>>>(out);
}